// round 9
// baseline (speedup 1.0000x reference)
#include <cuda_runtime.h>

#define ROWS 1024   // B*T
#define IDIM 256
#define HDIM 1024
#define ODIM 256

// ---------------- device scratch (no allocations allowed) ----------------
__device__ unsigned g_mk[(ROWS * HDIM) / 32];     // bernoulli mask (verified R6: partitionable, o0^o1)
__device__ float    g_xaug[ROWS * IDIM];
__device__ float    g_h[ROWS * HDIM];
__device__ double   g_psum[256];
__device__ int      g_pcnt[256];

// ---------------- threefry2x32, key = (0, 42) ----------------------------
__device__ __forceinline__ unsigned rotl32(unsigned v, int r) {
    return __funnelshift_l(v, v, r);
}

__device__ __forceinline__ void threefry_0_42(unsigned& x0, unsigned& x1) {
    const unsigned k0 = 0u, k1 = 42u;
    const unsigned k2 = k0 ^ k1 ^ 0x1BD11BDAu;
    x0 += k0; x1 += k1;
#define TF_R(r) { x0 += x1; x1 = rotl32(x1, r); x1 ^= x0; }
    TF_R(13) TF_R(15) TF_R(26) TF_R(6)   x0 += k1; x1 += k2 + 1u;
    TF_R(17) TF_R(29) TF_R(16) TF_R(24)  x0 += k2; x1 += k0 + 2u;
    TF_R(13) TF_R(15) TF_R(26) TF_R(6)   x0 += k0; x1 += k1 + 3u;
    TF_R(17) TF_R(29) TF_R(16) TF_R(24)  x0 += k1; x1 += k2 + 4u;
    TF_R(13) TF_R(15) TF_R(26) TF_R(6)   x0 += k2; x1 += k0 + 5u;
#undef TF_R
}

__global__ void mask_kernel(const float* __restrict__ freq) {
    int i = blockIdx.x * blockDim.x + threadIdx.x;   // 0 .. 2^20-1
    float fr = __ldg(&freq[i & 1023]);
    unsigned a0 = 0u, a1 = (unsigned)i;
    threefry_0_42(a0, a1);
    unsigned bits = a0 ^ a1;
    float u = __uint_as_float((bits >> 9) | 0x3f800000u) - 1.0f;
    unsigned b = __ballot_sync(0xffffffffu, u < fr);
    if ((threadIdx.x & 31) == 0) g_mk[i >> 5] = b;
}

// ---------------- argaug v2.1: 4-shift sliding window, DOUBLE prefix norms
__global__ void argaug_kernel(const float* __restrict__ x, const float* __restrict__ y) {
    __shared__ float  sx[256];
    __shared__ float  sy[256];
    __shared__ float  xsp[400];    // padded interp x: xsp[3+j] = xs[j]; zeros outside
    __shared__ double P[392];      // DOUBLE prefix sums of xs^2 (fp32 scan cancels catastrophically)
    __shared__ float  pd0[640];    // partial dots, q-segment 0, indexed by shift
    __shared__ float  pd1[640];    // partial dots, q-segment 1
    __shared__ double csum[16];
    __shared__ float  rv[256];
    __shared__ int    ri[256];
    __shared__ float  s_ny;
    __shared__ float  s_bestsim;
    __shared__ int    s_bestK, s_bestS;

    const int row = blockIdx.x;
    const int tid = threadIdx.x;
    const int wid = tid >> 5, lane = tid & 31;

    sx[tid] = x[row * IDIM + tid];
    float yv = y[row * IDIM + tid];
    sy[tid] = yv;
    rv[tid] = yv * yv;
    if (tid < 3) xsp[tid] = 0.0f;   // low pad, constant across thetas
    __syncthreads();
    for (int w = 128; w; w >>= 1) {
        if (tid < w) rv[tid] += rv[tid + w];
        __syncthreads();
    }
    if (tid == 0) {
        s_ny = sqrtf(rv[0]);
        s_bestsim = 0.0f;
        s_bestK = 128; s_bestS = 0;
    }
    __syncthreads();
    const float ny = s_ny;

    const int Ktab[9] = {128, 160, 192, 224, 256, 288, 320, 352, 384};

    for (int it = 0; it < 9; ++it) {
        const int K = Ktab[it];
        const double ratio = 256.0 / (double)K;   // numpy float64 semantics
        for (int j = tid; j < K; j += 256)
            xsp[3 + j] = sx[(int)floor((double)j * ratio)];
        if (tid < 12) xsp[K + 3 + tid] = 0.0f;
        __syncthreads();

        // prefix sums of xs^2 in double (warp-chunked scan; K multiple of 32)
        const int nchunk = K >> 5;
        for (int c = wid; c < nchunk; c += 8) {
            int j = c * 32 + lane;
            float xv = xsp[3 + j];
            double v = (double)xv * (double)xv;
#pragma unroll
            for (int o = 1; o < 32; o <<= 1) {
                double t = __shfl_up_sync(0xffffffffu, v, o);
                if (lane >= o) v += t;
            }
            P[1 + j] = v;
            if (lane == 31) csum[c] = v;
        }
        __syncthreads();
        if (tid == 0) {
            P[0] = 0.0;
            double run = 0.0;
            for (int c = 0; c < nchunk; ++c) { double t = csum[c]; csum[c] = run; run += t; }
        }
        __syncthreads();
        for (int j = tid; j < K; j += 256) P[1 + j] += csum[j >> 5];

        // units: group of 4 shifts x 2 q-segments
        const int ns = K + 255;
        const int G = (ns + 3) >> 2;
        const int U = 2 * G;
        for (int u = tid; u < U; u += 256) {
            const int g = u >> 1, seg = u & 1;
            const int s0 = 4 * g;
            int qlo = 252 - s0; if (qlo < 0) qlo = 0;
            int qhi = K + 254 - s0; if (qhi > 255) qhi = 255;
            const int len = qhi - qlo + 1;
            const int qm = qlo + ((len + 1) >> 1);
            const int qa = seg ? qm : qlo;
            const int qb = seg ? qhi : qm - 1;
            float d0 = 0.0f, d1 = 0.0f, d2 = 0.0f, d3 = 0.0f;
            const int ib = qa + s0 - 252;    // xsp idx for d=0 at q=qa
            float w0 = xsp[ib], w1 = xsp[ib + 1], w2 = xsp[ib + 2], w3 = xsp[ib + 3];
            int off = 4;
#pragma unroll 4
            for (int q = qa; q <= qb; ++q) {
                float yq = sy[q];
                d0 = fmaf(w0, yq, d0);
                d1 = fmaf(w1, yq, d1);
                d2 = fmaf(w2, yq, d2);
                d3 = fmaf(w3, yq, d3);
                w0 = w1; w1 = w2; w2 = w3; w3 = xsp[ib + off];
                ++off;
            }
            float* pd = seg ? pd1 : pd0;
            pd[s0 + 0] = d0; pd[s0 + 1] = d1; pd[s0 + 2] = d2; pd[s0 + 3] = d3;
        }
        __syncthreads();

        // per-shift sim + local argmax
        float lbest = -3.4e38f;
        int   lidx  = 0x7fffffff;
        for (int s = tid; s < ns; s += 256) {
            float dot = pd0[s] + pd1[s];
            int k0 = s - 255; if (k0 < 0) k0 = 0;
            int k1 = s;       if (k1 > K - 1) k1 = K - 1;
            float nrm = (float)(P[k1 + 1] - P[k0]);
            float sim = dot / (ny * sqrtf(nrm));
            if (sim > lbest) { lbest = sim; lidx = s; }
        }
        rv[tid] = lbest; ri[tid] = lidx;
        __syncthreads();
        for (int w = 128; w; w >>= 1) {
            if (tid < w) {
                float ov = rv[tid + w]; int oi = ri[tid + w];
                if (ov > rv[tid] || (ov == rv[tid] && oi < ri[tid])) {
                    rv[tid] = ov; ri[tid] = oi;
                }
            }
            __syncthreads();
        }
        if (tid == 0) {
            float sm = rv[0];
            if (it == 0) {
                s_bestK = K; s_bestS = ri[0];
                if (sm > 0.0f) s_bestsim = sm;
            } else if (s_bestsim < sm) {
                s_bestsim = sm; s_bestK = K; s_bestS = ri[0];
            }
        }
        __syncthreads();
    }

    const int K = s_bestK, s = s_bestS;
    const double ratio = 256.0 / (double)K;
    const int k = s + tid - 255;
    float v = 0.0f;
    if (k >= 0 && k < K) v = sx[(int)floor((double)k * ratio)];
    g_xaug[row * IDIM + tid] = v;
}

// ---------------- GEMM1: h = (xaug @ W1 + b1) * mk  (64x64, double-buffered)
__global__ void gemm1_kernel(const float* __restrict__ W1, const float* __restrict__ b1) {
    const int K = IDIM, N = HDIM;
    __shared__ float As[2][16][64];
    __shared__ float Bs[2][16][64];
    const int tid = threadIdx.x;
    const int tx = tid & 15, ty = tid >> 4;
    const int rowBase = blockIdx.y * 64, colBase = blockIdx.x * 64;
    const int aRow = tid >> 2, aK4 = tid & 3;
    const int bK = tid >> 4, bC4 = tid & 15;
    const float* A = g_xaug;

    float acc[4][4];
#pragma unroll
    for (int i = 0; i < 4; ++i)
#pragma unroll
        for (int j = 0; j < 4; ++j) acc[i][j] = 0.0f;

    {
        float4 av = *(const float4*)(A + (rowBase + aRow) * K + aK4 * 4);
        As[0][aK4 * 4 + 0][aRow] = av.x;
        As[0][aK4 * 4 + 1][aRow] = av.y;
        As[0][aK4 * 4 + 2][aRow] = av.z;
        As[0][aK4 * 4 + 3][aRow] = av.w;
        float4 bv = *(const float4*)(W1 + bK * N + colBase + bC4 * 4);
        *(float4*)&Bs[0][bK][bC4 * 4] = bv;
    }
    __syncthreads();

    const int NT = K / 16;
    for (int kt = 0; kt < NT; ++kt) {
        const int cur = kt & 1;
        float4 av, bv;
        if (kt + 1 < NT) {
            const int k0 = (kt + 1) * 16;
            av = *(const float4*)(A + (rowBase + aRow) * K + k0 + aK4 * 4);
            bv = *(const float4*)(W1 + (k0 + bK) * N + colBase + bC4 * 4);
        }
#pragma unroll
        for (int kk = 0; kk < 16; ++kk) {
            float4 a4 = *(const float4*)&As[cur][kk][ty * 4];
            float4 b4 = *(const float4*)&Bs[cur][kk][tx * 4];
            float am[4] = {a4.x, a4.y, a4.z, a4.w};
            float bn[4] = {b4.x, b4.y, b4.z, b4.w};
#pragma unroll
            for (int i = 0; i < 4; ++i)
#pragma unroll
                for (int j = 0; j < 4; ++j)
                    acc[i][j] = fmaf(am[i], bn[j], acc[i][j]);
        }
        if (kt + 1 < NT) {
            const int nxt = cur ^ 1;
            As[nxt][aK4 * 4 + 0][aRow] = av.x;
            As[nxt][aK4 * 4 + 1][aRow] = av.y;
            As[nxt][aK4 * 4 + 2][aRow] = av.z;
            As[nxt][aK4 * 4 + 3][aRow] = av.w;
            *(float4*)&Bs[nxt][bK][bC4 * 4] = bv;
        }
        __syncthreads();
    }
#pragma unroll
    for (int i = 0; i < 4; ++i) {
        const int r = rowBase + ty * 4 + i;
#pragma unroll
        for (int j = 0; j < 4; ++j) {
            const int c = colBase + tx * 4 + j;
            float v = acc[i][j] + __ldg(&b1[c]);
            const unsigned lin = (unsigned)(r * HDIM + c);
            const unsigned bit = (g_mk[lin >> 5] >> (lin & 31u)) & 1u;
            g_h[lin] = bit ? v : 0.0f;
        }
    }
}

// ---------------- GEMM2: out = h @ W2 + b2 + xaug ; fused masked MSE -----
// 16x64 tiles -> 256 blocks; double-buffered.
__global__ void gemm2_kernel(const float* __restrict__ W2, const float* __restrict__ b2,
                             const float* __restrict__ y, float* __restrict__ outp) {
    const int K = HDIM, N = ODIM;
    __shared__ float As[2][16][16];
    __shared__ float Bs[2][16][64];
    __shared__ double sred[256];
    __shared__ int    cred[256];
    const int tid = threadIdx.x;
    const int tx = tid & 15, ty = tid >> 4;
    const int rowBase = blockIdx.y * 16, colBase = blockIdx.x * 64;
    const int aRow = tid >> 2, aK4 = tid & 3;   // valid for tid < 64
    const int bK = tid >> 4, bC4 = tid & 15;
    const float* A = g_h;

    float acc[4] = {0.0f, 0.0f, 0.0f, 0.0f};

    if (tid < 64) {
        float4 av = *(const float4*)(A + (rowBase + aRow) * K + aK4 * 4);
        As[0][aK4 * 4 + 0][aRow] = av.x;
        As[0][aK4 * 4 + 1][aRow] = av.y;
        As[0][aK4 * 4 + 2][aRow] = av.z;
        As[0][aK4 * 4 + 3][aRow] = av.w;
    }
    {
        float4 bv = *(const float4*)(W2 + bK * N + colBase + bC4 * 4);
        *(float4*)&Bs[0][bK][bC4 * 4] = bv;
    }
    __syncthreads();

    const int NT = K / 16;   // 64
    for (int kt = 0; kt < NT; ++kt) {
        const int cur = kt & 1;
        float4 av, bv;
        if (kt + 1 < NT) {
            const int k0 = (kt + 1) * 16;
            if (tid < 64)
                av = *(const float4*)(A + (rowBase + aRow) * K + k0 + aK4 * 4);
            bv = *(const float4*)(W2 + (k0 + bK) * N + colBase + bC4 * 4);
        }
#pragma unroll
        for (int kk = 0; kk < 16; ++kk) {
            float a = As[cur][kk][ty];
            float4 b4 = *(const float4*)&Bs[cur][kk][tx * 4];
            acc[0] = fmaf(a, b4.x, acc[0]);
            acc[1] = fmaf(a, b4.y, acc[1]);
            acc[2] = fmaf(a, b4.z, acc[2]);
            acc[3] = fmaf(a, b4.w, acc[3]);
        }
        if (kt + 1 < NT) {
            const int nxt = cur ^ 1;
            if (tid < 64) {
                As[nxt][aK4 * 4 + 0][aRow] = av.x;
                As[nxt][aK4 * 4 + 1][aRow] = av.y;
                As[nxt][aK4 * 4 + 2][aRow] = av.z;
                As[nxt][aK4 * 4 + 3][aRow] = av.w;
            }
            *(float4*)&Bs[nxt][bK][bC4 * 4] = bv;
        }
        __syncthreads();
    }

    double lsum = 0.0;
    int lcnt = 0;
    {
        const int r = rowBase + ty;
#pragma unroll
        for (int j = 0; j < 4; ++j) {
            const int c = colBase + tx * 4 + j;
            float v = acc[j] + __ldg(&b2[c]) + g_xaug[r * ODIM + c];
            outp[r * ODIM + c] = v;
            float yv = y[r * ODIM + c];
            if (yv != 0.0f) {
                float d = v - yv;
                lsum += (double)d * (double)d;
                lcnt++;
            }
        }
    }
    sred[tid] = lsum; cred[tid] = lcnt;
    __syncthreads();
    for (int w = 128; w; w >>= 1) {
        if (tid < w) { sred[tid] += sred[tid + w]; cred[tid] += cred[tid + w]; }
        __syncthreads();
    }
    if (tid == 0) {
        const int bid = blockIdx.y * gridDim.x + blockIdx.x;
        g_psum[bid] = sred[0];
        g_pcnt[bid] = cred[0];
    }
}

__global__ void finalize_kernel(float* __restrict__ loss_out) {
    const int tid = threadIdx.x;   // 256 threads
    __shared__ double ss[256];
    __shared__ int    sc[256];
    ss[tid] = g_psum[tid];
    sc[tid] = g_pcnt[tid];
    __syncthreads();
    for (int w = 128; w; w >>= 1) {
        if (tid < w) { ss[tid] += ss[tid + w]; sc[tid] += sc[tid + w]; }
        __syncthreads();
    }
    if (tid == 0) loss_out[0] = (float)(ss[0] / (double)sc[0]);
}

extern "C" void kernel_launch(void* const* d_in, const int* in_sizes, int n_in,
                              void* d_out, int out_size) {
    const float* x    = (const float*)d_in[0];
    const float* y    = (const float*)d_in[1];
    const float* W1   = (const float*)d_in[2];
    const float* b1   = (const float*)d_in[3];
    const float* W2   = (const float*)d_in[4];
    const float* b2   = (const float*)d_in[5];
    const float* freq = (const float*)d_in[6];

    float* out = (float*)d_out;
    const bool has_loss = (out_size > ROWS * ODIM);
    float* outmat = has_loss ? out + 1 : out;

    mask_kernel<<<4096, 256>>>(freq);
    argaug_kernel<<<1024, 256>>>(x, y);
    gemm1_kernel<<<dim3(16, 16), 256>>>(W1, b1);
    gemm2_kernel<<<dim3(4, 64), 256>>>(W2, b2, y, outmat);
    if (has_loss) finalize_kernel<<<1, 256>>>(out);
}

// round 10
// speedup vs baseline: 1.1574x; 1.1574x over previous
#include <cuda_runtime.h>

#define ROWS 1024   // B*T
#define IDIM 256
#define HDIM 1024
#define ODIM 256
#define NSPLIT 4

// ---------------- device scratch (no allocations allowed) ----------------
__device__ unsigned g_mk[(ROWS * HDIM) / 32];     // bernoulli mask (verified R6: partitionable, o0^o1)
__device__ float    g_xaug[ROWS * IDIM];
__device__ float    g_h[ROWS * HDIM];
__device__ float    g_part[NSPLIT * ROWS * ODIM]; // split-K partials (4 MB)
__device__ double   g_psum[256];
__device__ int      g_pcnt[256];

// ---------------- threefry2x32, key = (0, 42) ----------------------------
__device__ __forceinline__ unsigned rotl32(unsigned v, int r) {
    return __funnelshift_l(v, v, r);
}

__device__ __forceinline__ void threefry_0_42(unsigned& x0, unsigned& x1) {
    const unsigned k0 = 0u, k1 = 42u;
    const unsigned k2 = k0 ^ k1 ^ 0x1BD11BDAu;
    x0 += k0; x1 += k1;
#define TF_R(r) { x0 += x1; x1 = rotl32(x1, r); x1 ^= x0; }
    TF_R(13) TF_R(15) TF_R(26) TF_R(6)   x0 += k1; x1 += k2 + 1u;
    TF_R(17) TF_R(29) TF_R(16) TF_R(24)  x0 += k2; x1 += k0 + 2u;
    TF_R(13) TF_R(15) TF_R(26) TF_R(6)   x0 += k0; x1 += k1 + 3u;
    TF_R(17) TF_R(29) TF_R(16) TF_R(24)  x0 += k1; x1 += k2 + 4u;
    TF_R(13) TF_R(15) TF_R(26) TF_R(6)   x0 += k2; x1 += k0 + 5u;
#undef TF_R
}

__global__ void mask_kernel(const float* __restrict__ freq) {
    int i = blockIdx.x * blockDim.x + threadIdx.x;   // 0 .. 2^20-1
    float fr = __ldg(&freq[i & 1023]);
    unsigned a0 = 0u, a1 = (unsigned)i;
    threefry_0_42(a0, a1);
    unsigned bits = a0 ^ a1;
    float u = __uint_as_float((bits >> 9) | 0x3f800000u) - 1.0f;
    unsigned b = __ballot_sync(0xffffffffu, u < fr);
    if ((threadIdx.x & 31) == 0) g_mk[i >> 5] = b;
}

// ---------------- argaug v2.2: 4-shift x 4-segment units, warp argmax ----
__global__ void argaug_kernel(const float* __restrict__ x, const float* __restrict__ y) {
    __shared__ float  sx[256];
    __shared__ float  sy[256];
    __shared__ float  xsp[400];    // padded interp x: xsp[3+j] = xs[j]; zeros outside
    __shared__ double P[392];      // DOUBLE prefix sums of xs^2 (fp32 cancels, proven R8->R9)
    __shared__ float  pds[4][640]; // partial dots per q-segment, indexed by shift
    __shared__ double csum[16];
    __shared__ float  rv[256];     // also reused for ny reduction
    __shared__ int    ri[8];
    __shared__ float  s_ny;
    __shared__ float  s_bestsim;
    __shared__ int    s_bestK, s_bestS;

    const int row = blockIdx.x;
    const int tid = threadIdx.x;
    const int wid = tid >> 5, lane = tid & 31;

    sx[tid] = x[row * IDIM + tid];
    float yv = y[row * IDIM + tid];
    sy[tid] = yv;
    rv[tid] = yv * yv;
    if (tid < 3) xsp[tid] = 0.0f;   // low pad, constant across thetas
    __syncthreads();
    for (int w = 128; w; w >>= 1) {
        if (tid < w) rv[tid] += rv[tid + w];
        __syncthreads();
    }
    if (tid == 0) {
        s_ny = sqrtf(rv[0]);
        s_bestsim = 0.0f;
        s_bestK = 128; s_bestS = 0;
    }
    __syncthreads();
    const float ny = s_ny;

    const int Ktab[9] = {128, 160, 192, 224, 256, 288, 320, 352, 384};

    for (int it = 0; it < 9; ++it) {
        const int K = Ktab[it];
        const double ratio = 256.0 / (double)K;   // numpy float64 semantics
        for (int j = tid; j < K; j += 256)
            xsp[3 + j] = sx[(int)floor((double)j * ratio)];
        if (tid < 12) xsp[K + 3 + tid] = 0.0f;
        __syncthreads();

        // prefix sums of xs^2 in double (warp-chunked scan; K multiple of 32)
        const int nchunk = K >> 5;
        for (int c = wid; c < nchunk; c += 8) {
            int j = c * 32 + lane;
            float xv = xsp[3 + j];
            double v = (double)xv * (double)xv;
#pragma unroll
            for (int o = 1; o < 32; o <<= 1) {
                double t = __shfl_up_sync(0xffffffffu, v, o);
                if (lane >= o) v += t;
            }
            P[1 + j] = v;
            if (lane == 31) csum[c] = v;
        }
        __syncthreads();
        if (tid == 0) {
            P[0] = 0.0;
            double run = 0.0;
            for (int c = 0; c < nchunk; ++c) { double t = csum[c]; csum[c] = run; run += t; }
        }
        __syncthreads();
        for (int j = tid; j < K; j += 256) P[1 + j] += csum[j >> 5];

        // units: group of 4 shifts x 4 q-segments
        const int ns = K + 255;
        const int G = (ns + 3) >> 2;
        const int U = 4 * G;
        for (int u = tid; u < U; u += 256) {
            const int g = u >> 2, seg = u & 3;
            const int s0 = 4 * g;
            int qlo = 252 - s0; if (qlo < 0) qlo = 0;
            int qhi = K + 254 - s0; if (qhi > 255) qhi = 255;
            const int len = qhi - qlo + 1;
            const int qa = qlo + ((len * seg) >> 2);
            const int qb = qlo + ((len * (seg + 1)) >> 2) - 1;
            float d0 = 0.0f, d1 = 0.0f, d2 = 0.0f, d3 = 0.0f;
            const int ib = qa + s0 - 252;    // xsp idx for d=0 at q=qa
            float w0 = xsp[ib], w1 = xsp[ib + 1], w2 = xsp[ib + 2], w3 = xsp[ib + 3];
            int off = 4;
#pragma unroll 4
            for (int q = qa; q <= qb; ++q) {
                float yq = sy[q];
                d0 = fmaf(w0, yq, d0);
                d1 = fmaf(w1, yq, d1);
                d2 = fmaf(w2, yq, d2);
                d3 = fmaf(w3, yq, d3);
                w0 = w1; w1 = w2; w2 = w3; w3 = xsp[ib + off];
                ++off;
            }
            pds[seg][s0 + 0] = d0; pds[seg][s0 + 1] = d1;
            pds[seg][s0 + 2] = d2; pds[seg][s0 + 3] = d3;
        }
        __syncthreads();

        // per-shift sim + argmax (warp shuffle reduce, idx-min tiebreak)
        float lbest = -3.4e38f;
        int   lidx  = 0x7fffffff;
        for (int s = tid; s < ns; s += 256) {
            float dot = (pds[0][s] + pds[1][s]) + (pds[2][s] + pds[3][s]);
            int k0 = s - 255; if (k0 < 0) k0 = 0;
            int k1 = s;       if (k1 > K - 1) k1 = K - 1;
            float nrm = (float)(P[k1 + 1] - P[k0]);
            float sim = dot / (ny * sqrtf(nrm));
            if (sim > lbest) { lbest = sim; lidx = s; }
        }
#pragma unroll
        for (int o = 16; o; o >>= 1) {
            float ov = __shfl_down_sync(0xffffffffu, lbest, o);
            int   oi = __shfl_down_sync(0xffffffffu, lidx, o);
            if (ov > lbest || (ov == lbest && oi < lidx)) { lbest = ov; lidx = oi; }
        }
        if (lane == 0) { rv[wid] = lbest; ri[wid] = lidx; }
        __syncthreads();
        if (tid == 0) {
            float bb = rv[0]; int bi = ri[0];
#pragma unroll
            for (int w = 1; w < 8; ++w) {
                if (rv[w] > bb || (rv[w] == bb && ri[w] < bi)) { bb = rv[w]; bi = ri[w]; }
            }
            if (it == 0) {
                s_bestK = K; s_bestS = bi;
                if (bb > 0.0f) s_bestsim = bb;
            } else if (s_bestsim < bb) {
                s_bestsim = bb; s_bestK = K; s_bestS = bi;
            }
        }
        __syncthreads();
    }

    const int K = s_bestK, s = s_bestS;
    const double ratio = 256.0 / (double)K;
    const int k = s + tid - 255;
    float v = 0.0f;
    if (k >= 0 && k < K) v = sx[(int)floor((double)k * ratio)];
    g_xaug[row * IDIM + tid] = v;
}

// ---------------- GEMM1: h = (xaug @ W1 + b1) * mk ------------------------
// 16x64 tile, 128 threads, 2x4 accum, KTILE=32, double-buffered, grid 1024.
__global__ void gemm1_kernel(const float* __restrict__ W1, const float* __restrict__ b1) {
    const int K = IDIM, N = HDIM;
    __shared__ float As[2][16][33];   // [row][k], padded: broadcast reads, cf stores
    __shared__ float Bs[2][32][64];   // [k][col]
    const int tid = threadIdx.x;                 // 128
    const int tx = tid & 15, ty = tid >> 4;      // tx: col grp, ty: row grp (2 rows)
    const int rowBase = blockIdx.y * 16, colBase = blockIdx.x * 64;
    const int aRow = tid >> 3, aK4 = tid & 7;    // A: 16r x 32k = 128 f4, 1/thread
    const int bK = tid >> 4, bC4 = tid & 15;     // B: 4 f4/thread, k = bK+8m
    const int ty2 = ty * 2;
    const float* A = g_xaug;

    float acc[2][4];
#pragma unroll
    for (int i = 0; i < 2; ++i)
#pragma unroll
        for (int j = 0; j < 4; ++j) acc[i][j] = 0.0f;

    // preload tile 0
    {
        float4 av = *(const float4*)(A + (rowBase + aRow) * K + aK4 * 4);
        As[0][aRow][aK4 * 4 + 0] = av.x;
        As[0][aRow][aK4 * 4 + 1] = av.y;
        As[0][aRow][aK4 * 4 + 2] = av.z;
        As[0][aRow][aK4 * 4 + 3] = av.w;
#pragma unroll
        for (int m = 0; m < 4; ++m) {
            float4 bv = *(const float4*)(W1 + (bK + 8 * m) * N + colBase + bC4 * 4);
            *(float4*)&Bs[0][bK + 8 * m][bC4 * 4] = bv;
        }
    }
    __syncthreads();

    const int NT = K / 32;   // 8
    for (int kt = 0; kt < NT; ++kt) {
        const int cur = kt & 1;
        float4 av, bv0, bv1, bv2, bv3;
        if (kt + 1 < NT) {
            const int k0 = (kt + 1) * 32;
            av  = *(const float4*)(A + (rowBase + aRow) * K + k0 + aK4 * 4);
            bv0 = *(const float4*)(W1 + (k0 + bK +  0) * N + colBase + bC4 * 4);
            bv1 = *(const float4*)(W1 + (k0 + bK +  8) * N + colBase + bC4 * 4);
            bv2 = *(const float4*)(W1 + (k0 + bK + 16) * N + colBase + bC4 * 4);
            bv3 = *(const float4*)(W1 + (k0 + bK + 24) * N + colBase + bC4 * 4);
        }
#pragma unroll
        for (int kk = 0; kk < 32; ++kk) {
            float a0 = As[cur][ty2][kk];
            float a1 = As[cur][ty2 + 1][kk];
            float4 b4 = *(const float4*)&Bs[cur][kk][tx * 4];
            acc[0][0] = fmaf(a0, b4.x, acc[0][0]);
            acc[0][1] = fmaf(a0, b4.y, acc[0][1]);
            acc[0][2] = fmaf(a0, b4.z, acc[0][2]);
            acc[0][3] = fmaf(a0, b4.w, acc[0][3]);
            acc[1][0] = fmaf(a1, b4.x, acc[1][0]);
            acc[1][1] = fmaf(a1, b4.y, acc[1][1]);
            acc[1][2] = fmaf(a1, b4.z, acc[1][2]);
            acc[1][3] = fmaf(a1, b4.w, acc[1][3]);
        }
        if (kt + 1 < NT) {
            const int nxt = cur ^ 1;
            As[nxt][aRow][aK4 * 4 + 0] = av.x;
            As[nxt][aRow][aK4 * 4 + 1] = av.y;
            As[nxt][aRow][aK4 * 4 + 2] = av.z;
            As[nxt][aRow][aK4 * 4 + 3] = av.w;
            *(float4*)&Bs[nxt][bK +  0][bC4 * 4] = bv0;
            *(float4*)&Bs[nxt][bK +  8][bC4 * 4] = bv1;
            *(float4*)&Bs[nxt][bK + 16][bC4 * 4] = bv2;
            *(float4*)&Bs[nxt][bK + 24][bC4 * 4] = bv3;
        }
        __syncthreads();
    }

    float4 b1v = *(const float4*)(b1 + colBase + tx * 4);
#pragma unroll
    for (int i = 0; i < 2; ++i) {
        const int r = rowBase + ty2 + i;
        const int c = colBase + tx * 4;
        const unsigned lin = (unsigned)(r * HDIM + c);
        const unsigned word = g_mk[lin >> 5];
        float4 o;
        o.x = ((word >> ((lin + 0) & 31u)) & 1u) ? (acc[i][0] + b1v.x) : 0.0f;
        o.y = ((word >> ((lin + 1) & 31u)) & 1u) ? (acc[i][1] + b1v.y) : 0.0f;
        o.z = ((word >> ((lin + 2) & 31u)) & 1u) ? (acc[i][2] + b1v.z) : 0.0f;
        o.w = ((word >> ((lin + 3) & 31u)) & 1u) ? (acc[i][3] + b1v.w) : 0.0f;
        *(float4*)(g_h + lin) = o;
    }
}

// ---------------- GEMM2 split-K: partial[z] = h[:, z*256:(z+1)*256] @ W2[...]
__global__ void gemm2_kernel(const float* __restrict__ W2) {
    const int K = HDIM, N = ODIM;
    __shared__ float As[2][16][33];
    __shared__ float Bs[2][32][64];
    const int tid = threadIdx.x;
    const int tx = tid & 15, ty = tid >> 4;
    const int rowBase = blockIdx.y * 16, colBase = blockIdx.x * 64;
    const int kbase = blockIdx.z * 256;
    const int aRow = tid >> 3, aK4 = tid & 7;
    const int bK = tid >> 4, bC4 = tid & 15;
    const int ty2 = ty * 2;
    const float* A = g_h;

    float acc[2][4];
#pragma unroll
    for (int i = 0; i < 2; ++i)
#pragma unroll
        for (int j = 0; j < 4; ++j) acc[i][j] = 0.0f;

    {
        float4 av = *(const float4*)(A + (rowBase + aRow) * K + kbase + aK4 * 4);
        As[0][aRow][aK4 * 4 + 0] = av.x;
        As[0][aRow][aK4 * 4 + 1] = av.y;
        As[0][aRow][aK4 * 4 + 2] = av.z;
        As[0][aRow][aK4 * 4 + 3] = av.w;
#pragma unroll
        for (int m = 0; m < 4; ++m) {
            float4 bv = *(const float4*)(W2 + (kbase + bK + 8 * m) * N + colBase + bC4 * 4);
            *(float4*)&Bs[0][bK + 8 * m][bC4 * 4] = bv;
        }
    }
    __syncthreads();

    const int NT = 256 / 32;   // 8
    for (int kt = 0; kt < NT; ++kt) {
        const int cur = kt & 1;
        float4 av, bv0, bv1, bv2, bv3;
        if (kt + 1 < NT) {
            const int k0 = kbase + (kt + 1) * 32;
            av  = *(const float4*)(A + (rowBase + aRow) * K + k0 + aK4 * 4);
            bv0 = *(const float4*)(W2 + (k0 + bK +  0) * N + colBase + bC4 * 4);
            bv1 = *(const float4*)(W2 + (k0 + bK +  8) * N + colBase + bC4 * 4);
            bv2 = *(const float4*)(W2 + (k0 + bK + 16) * N + colBase + bC4 * 4);
            bv3 = *(const float4*)(W2 + (k0 + bK + 24) * N + colBase + bC4 * 4);
        }
#pragma unroll
        for (int kk = 0; kk < 32; ++kk) {
            float a0 = As[cur][ty2][kk];
            float a1 = As[cur][ty2 + 1][kk];
            float4 b4 = *(const float4*)&Bs[cur][kk][tx * 4];
            acc[0][0] = fmaf(a0, b4.x, acc[0][0]);
            acc[0][1] = fmaf(a0, b4.y, acc[0][1]);
            acc[0][2] = fmaf(a0, b4.z, acc[0][2]);
            acc[0][3] = fmaf(a0, b4.w, acc[0][3]);
            acc[1][0] = fmaf(a1, b4.x, acc[1][0]);
            acc[1][1] = fmaf(a1, b4.y, acc[1][1]);
            acc[1][2] = fmaf(a1, b4.z, acc[1][2]);
            acc[1][3] = fmaf(a1, b4.w, acc[1][3]);
        }
        if (kt + 1 < NT) {
            const int nxt = cur ^ 1;
            As[nxt][aRow][aK4 * 4 + 0] = av.x;
            As[nxt][aRow][aK4 * 4 + 1] = av.y;
            As[nxt][aRow][aK4 * 4 + 2] = av.z;
            As[nxt][aRow][aK4 * 4 + 3] = av.w;
            *(float4*)&Bs[nxt][bK +  0][bC4 * 4] = bv0;
            *(float4*)&Bs[nxt][bK +  8][bC4 * 4] = bv1;
            *(float4*)&Bs[nxt][bK + 16][bC4 * 4] = bv2;
            *(float4*)&Bs[nxt][bK + 24][bC4 * 4] = bv3;
        }
        __syncthreads();
    }

    float* dst = g_part + (size_t)blockIdx.z * (ROWS * ODIM);
#pragma unroll
    for (int i = 0; i < 2; ++i) {
        const int r = rowBase + ty2 + i;
        const int c = colBase + tx * 4;
        *(float4*)(dst + r * ODIM + c) =
            make_float4(acc[i][0], acc[i][1], acc[i][2], acc[i][3]);
    }
}

// ---------------- epilogue: out = Σ partials + b2 + xaug ; masked MSE ----
__global__ void epilogue_kernel(const float* __restrict__ b2, const float* __restrict__ y,
                                float* __restrict__ outp) {
    __shared__ double sred[256];
    __shared__ int    cred[256];
    const int tid = threadIdx.x;
    const int idx = blockIdx.x * 256 + tid;          // f4 index, 65536 total
    const int c = (idx & 63) * 4;

    const float4* p0 = (const float4*)g_part;
    const float4* p1 = p0 + (ROWS * ODIM / 4);
    const float4* p2 = p1 + (ROWS * ODIM / 4);
    const float4* p3 = p2 + (ROWS * ODIM / 4);

    float4 a = p0[idx], b = p1[idx], cc = p2[idx], d = p3[idx];
    float4 xv = ((const float4*)g_xaug)[idx];
    float4 bv = *(const float4*)(b2 + c);
    float4 yv = ((const float4*)y)[idx];

    float v0 = (a.x + b.x) + (cc.x + d.x) + bv.x + xv.x;
    float v1 = (a.y + b.y) + (cc.y + d.y) + bv.y + xv.y;
    float v2 = (a.z + b.z) + (cc.z + d.z) + bv.z + xv.z;
    float v3 = (a.w + b.w) + (cc.w + d.w) + bv.w + xv.w;

    // outp may be 4-byte aligned only (out+1) -> scalar stores
    outp[idx * 4 + 0] = v0;
    outp[idx * 4 + 1] = v1;
    outp[idx * 4 + 2] = v2;
    outp[idx * 4 + 3] = v3;

    double lsum = 0.0; int lcnt = 0;
    if (yv.x != 0.0f) { float e = v0 - yv.x; lsum += (double)e * e; lcnt++; }
    if (yv.y != 0.0f) { float e = v1 - yv.y; lsum += (double)e * e; lcnt++; }
    if (yv.z != 0.0f) { float e = v2 - yv.z; lsum += (double)e * e; lcnt++; }
    if (yv.w != 0.0f) { float e = v3 - yv.w; lsum += (double)e * e; lcnt++; }

    sred[tid] = lsum; cred[tid] = lcnt;
    __syncthreads();
    for (int w = 128; w; w >>= 1) {
        if (tid < w) { sred[tid] += sred[tid + w]; cred[tid] += cred[tid + w]; }
        __syncthreads();
    }
    if (tid == 0) { g_psum[blockIdx.x] = sred[0]; g_pcnt[blockIdx.x] = cred[0]; }
}

__global__ void finalize_kernel(float* __restrict__ loss_out) {
    const int tid = threadIdx.x;   // 256
    __shared__ double ss[256];
    __shared__ int    sc[256];
    ss[tid] = g_psum[tid];
    sc[tid] = g_pcnt[tid];
    __syncthreads();
    for (int w = 128; w; w >>= 1) {
        if (tid < w) { ss[tid] += ss[tid + w]; sc[tid] += sc[tid + w]; }
        __syncthreads();
    }
    if (tid == 0) loss_out[0] = (float)(ss[0] / (double)sc[0]);
}

extern "C" void kernel_launch(void* const* d_in, const int* in_sizes, int n_in,
                              void* d_out, int out_size) {
    const float* x    = (const float*)d_in[0];
    const float* y    = (const float*)d_in[1];
    const float* W1   = (const float*)d_in[2];
    const float* b1   = (const float*)d_in[3];
    const float* W2   = (const float*)d_in[4];
    const float* b2   = (const float*)d_in[5];
    const float* freq = (const float*)d_in[6];

    float* out = (float*)d_out;
    const bool has_loss = (out_size > ROWS * ODIM);
    float* outmat = has_loss ? out + 1 : out;

    mask_kernel<<<4096, 256>>>(freq);
    argaug_kernel<<<1024, 256>>>(x, y);
    gemm1_kernel<<<dim3(HDIM / 64, ROWS / 16), 128>>>(W1, b1);
    gemm2_kernel<<<dim3(ODIM / 64, ROWS / 16, NSPLIT), 128>>>(W2);
    epilogue_kernel<<<256, 256>>>(b2, y, outmat);
    if (has_loss) finalize_kernel<<<1, 256>>>(out);
}